// round 13
// baseline (speedup 1.0000x reference)
#include <cuda_runtime.h>
#include <cuda_bf16.h>
#include <cuda_fp16.h>
#include <stdint.h>
#include <math.h>

#define N_NODES 100000
#define N_EDGES 1600000
#define HID 128
#define EPS 1e-5f

// ---------------- scratch (static device globals; no allocation) ----------------
__device__ float  d_h[N_NODES * HID];     // current activation (fp32)
__device__ __half d_t[N_NODES * HID];     // h @ W (fp16, pre-aggregation)
__device__ float  d_a[N_NODES * HID];     // aggregated (fp32, pre-BN) — fp16 here FAILS accuracy
__device__ float  d_t32[N_NODES * 32];    // head linear output
__device__ float  d_dinv[N_NODES];
__device__ int    d_cnt[N_NODES];
__device__ int    d_off[N_NODES];
__device__ int    d_cur[N_NODES];
__device__ int    d_total;
__device__ int2   d_epack[N_EDGES];       // {src, __float_as_int(w)}
__device__ float  d_sumL[4][HID], d_sqL[4][HID];
__device__ float  d_scale[HID], d_shift[HID];
__device__ float  d_scale32[32], d_shift32[32];
// packed fragments: uint4 = {bhi.x, bhi.y, blo.x, blo.y} per [kc][nt][lane]
__device__ uint4 d_fragP[3][8 * 16 * 32];
__device__ uint4 d_fragP32[8 * 4 * 32];

// ---------------- CSR build ----------------
__global__ void k_zero_cnt() {
    int i = blockIdx.x * blockDim.x + threadIdx.x;
    if (i < N_NODES) d_cnt[i] = 0;
    if (i < 512) { ((float*)d_sumL)[i] = 0.f; ((float*)d_sqL)[i] = 0.f; }
    if (i == 0) d_total = 0;
}

__global__ void k_count(const int* __restrict__ dst) {
    int e = blockIdx.x * blockDim.x + threadIdx.x;
    if (e < N_EDGES) atomicAdd(&d_cnt[dst[e]], 1);
}

// fused: segment allocation (block scan + global atomic) + dinv + cursor init
__global__ void k_alloc() {
    int i = blockIdx.x * 256 + threadIdx.x;
    int c = (i < N_NODES) ? d_cnt[i] : 0;
    int lane = threadIdx.x & 31, w = threadIdx.x >> 5;
    int v = c;
#pragma unroll
    for (int d = 1; d < 32; d <<= 1) {
        int t = __shfl_up_sync(0xFFFFFFFFu, v, d);
        if (lane >= d) v += t;
    }
    __shared__ int ws[8];
    __shared__ int base;
    if (lane == 31) ws[w] = v;
    __syncthreads();
    if (threadIdx.x == 0) {
        int s = 0;
#pragma unroll
        for (int k = 0; k < 8; k++) { int t = ws[k]; ws[k] = s; s += t; }
        base = atomicAdd(&d_total, s);
    }
    __syncthreads();
    if (i < N_NODES) {
        int o = base + ws[w] + v - c;
        d_off[i] = o;
        d_cur[i] = o;
        d_dinv[i] = rsqrtf((float)(c + 1));
    }
}

__global__ void k_scatter(const int* __restrict__ src, const int* __restrict__ dst) {
    int e = blockIdx.x * blockDim.x + threadIdx.x;
    if (e >= N_EDGES) return;
    int s = src[e], d = dst[e];
    int p = atomicAdd(&d_cur[d], 1);
    d_epack[p] = make_int2(s, __float_as_int(d_dinv[s] * d_dinv[d]));
}

// ---------------- encoder: h = relu(x @ We + be), x is [N,2] ----------------
__global__ void k_encoder(const float* __restrict__ x, const float* __restrict__ We,
                          const float* __restrict__ be) {
    int n = blockIdx.x;
    int c = threadIdx.x;
    float v = x[n * 2] * We[c] + x[n * 2 + 1] * We[HID + c] + be[c];
    d_h[n * HID + c] = fmaxf(v, 0.0f);
}

// ---------------- weight -> packed mma B-fragment preconvert ----------------
__global__ void k_wfrag(const float* __restrict__ W, uint4* __restrict__ fragP, int NT) {
    int idx = blockIdx.x * blockDim.x + threadIdx.x;
    int total = 8 * NT * 32;
    if (idx >= total) return;
    int lane = idx & 31;
    int nt = (idx >> 5) % NT;
    int kc = idx / (32 * NT);
    int N = NT * 8;
    int n = nt * 8 + (lane >> 2);
    int k0 = kc * 16 + (lane & 3) * 2;
    float w00 = W[k0 * N + n],      w01 = W[(k0 + 1) * N + n];
    float w10 = W[(k0 + 8) * N + n], w11 = W[(k0 + 9) * N + n];
    __nv_bfloat16 h00 = __float2bfloat16(w00), h01 = __float2bfloat16(w01);
    __nv_bfloat16 h10 = __float2bfloat16(w10), h11 = __float2bfloat16(w11);
    __nv_bfloat16 l00 = __float2bfloat16(w00 - __bfloat162float(h00));
    __nv_bfloat16 l01 = __float2bfloat16(w01 - __bfloat162float(h01));
    __nv_bfloat16 l10 = __float2bfloat16(w10 - __bfloat162float(h10));
    __nv_bfloat16 l11 = __float2bfloat16(w11 - __bfloat162float(h11));
    uint4 pv;
    pv.x = (uint32_t)__bfloat16_as_ushort(h00) | ((uint32_t)__bfloat16_as_ushort(h01) << 16);
    pv.y = (uint32_t)__bfloat16_as_ushort(h10) | ((uint32_t)__bfloat16_as_ushort(h11) << 16);
    pv.z = (uint32_t)__bfloat16_as_ushort(l00) | ((uint32_t)__bfloat16_as_ushort(l01) << 16);
    pv.w = (uint32_t)__bfloat16_as_ushort(l10) | ((uint32_t)__bfloat16_as_ushort(l11) << 16);
    fragP[idx] = pv;
}

#define MMA_BF16(ACC, A0, A1, A2, A3, BX, BY)                                          \
    asm volatile(                                                                      \
        "mma.sync.aligned.m16n8k16.row.col.f32.bf16.bf16.f32 "                         \
        "{%0,%1,%2,%3}, {%4,%5,%6,%7}, {%8,%9}, {%0,%1,%2,%3};"                        \
        : "+f"((ACC)[0]), "+f"((ACC)[1]), "+f"((ACC)[2]), "+f"((ACC)[3])               \
        : "r"(A0), "r"(A1), "r"(A2), "r"(A3), "r"(BX), "r"(BY))

// ---------------- shared A-tile fill: optional fused BN-apply + relu + residual ----------------
template <int APPLY, int WRITEH, int NTHREADS>
__device__ __forceinline__ void fill_A(float* __restrict__ hbuf,
                                       const float* __restrict__ abuf,
                                       __nv_bfloat16* a_s, int AS, int rowbase, int tid) {
    for (int i = tid; i < 128 * 32; i += NTHREADS) {
        int row = i >> 5, cg = i & 31;
        int gr = rowbase + row;
        float4 v = make_float4(0.f, 0.f, 0.f, 0.f);
        if (gr < N_NODES) {
            if (APPLY) {
                float4 a4 = ((const float4*)abuf)[gr * 32 + cg];
                float4 h4 = ((const float4*)hbuf)[gr * 32 + cg];
                int c0 = cg * 4;
                v.x = fmaxf(a4.x * d_scale[c0]     + d_shift[c0],     0.f) + h4.x;
                v.y = fmaxf(a4.y * d_scale[c0 + 1] + d_shift[c0 + 1], 0.f) + h4.y;
                v.z = fmaxf(a4.z * d_scale[c0 + 2] + d_shift[c0 + 2], 0.f) + h4.z;
                v.w = fmaxf(a4.w * d_scale[c0 + 3] + d_shift[c0 + 3], 0.f) + h4.w;
                if (WRITEH) ((float4*)hbuf)[gr * 32 + cg] = v;
            } else {
                v = ((const float4*)hbuf)[gr * 32 + cg];
            }
        }
        __nv_bfloat16 h0 = __float2bfloat16(v.x), h1 = __float2bfloat16(v.y);
        __nv_bfloat16 h2 = __float2bfloat16(v.z), h3 = __float2bfloat16(v.w);
        __nv_bfloat16 l0 = __float2bfloat16(v.x - __bfloat162float(h0));
        __nv_bfloat16 l1 = __float2bfloat16(v.y - __bfloat162float(h1));
        __nv_bfloat16 l2 = __float2bfloat16(v.z - __bfloat162float(h2));
        __nv_bfloat16 l3 = __float2bfloat16(v.w - __bfloat162float(h3));
        int e = row * 136 + cg * 4;
        uint32_t* ph = (uint32_t*)&a_s[e];
        uint32_t* pl = (uint32_t*)&a_s[AS + e];
        ph[0] = (uint32_t)__bfloat16_as_ushort(h0) | ((uint32_t)__bfloat16_as_ushort(h1) << 16);
        ph[1] = (uint32_t)__bfloat16_as_ushort(h2) | ((uint32_t)__bfloat16_as_ushort(h3) << 16);
        pl[0] = (uint32_t)__bfloat16_as_ushort(l0) | ((uint32_t)__bfloat16_as_ushort(l1) << 16);
        pl[1] = (uint32_t)__bfloat16_as_ushort(l2) | ((uint32_t)__bfloat16_as_ushort(l3) << 16);
    }
}

// ---------------- main HMMA GEMM: d_t[fp16] = A @ W, 512 threads, warp=m16n64 ----------------
template <int APPLY>
__global__ void __launch_bounds__(512, 2) k_gemm_split(float* __restrict__ hbuf,
                                                       const float* __restrict__ abuf,
                                                       const uint4* __restrict__ fragP,
                                                       __half* __restrict__ dst) {
    extern __shared__ __nv_bfloat16 a_s[];  // [2][128][136] bf16 (hi then lo)
    const int AS = 128 * 136;
    int tid = threadIdx.x, lane = tid & 31, wid = tid >> 5;
    int rowbase = blockIdx.x * 128;

    fill_A<APPLY, 1, 512>(hbuf, abuf, a_s, AS, rowbase, tid);
    __syncthreads();

    float acc[8][4];
#pragma unroll
    for (int nt = 0; nt < 8; nt++)
#pragma unroll
        for (int j = 0; j < 4; j++) acc[nt][j] = 0.0f;

    int rloc = (wid >> 1) * 16 + (lane >> 2);
    int kcol = (lane & 3) * 2;
    int nbase = (wid & 1) * 8;

#pragma unroll
    for (int kc = 0; kc < 8; kc++) {
        int k0 = kc * 16 + kcol;
        uint32_t ah0 = *(const uint32_t*)&a_s[rloc * 136 + k0];
        uint32_t ah1 = *(const uint32_t*)&a_s[(rloc + 8) * 136 + k0];
        uint32_t ah2 = *(const uint32_t*)&a_s[rloc * 136 + k0 + 8];
        uint32_t ah3 = *(const uint32_t*)&a_s[(rloc + 8) * 136 + k0 + 8];
        uint32_t al0 = *(const uint32_t*)&a_s[AS + rloc * 136 + k0];
        uint32_t al1 = *(const uint32_t*)&a_s[AS + (rloc + 8) * 136 + k0];
        uint32_t al2 = *(const uint32_t*)&a_s[AS + rloc * 136 + k0 + 8];
        uint32_t al3 = *(const uint32_t*)&a_s[AS + (rloc + 8) * 136 + k0 + 8];
        const uint4* FP = fragP + kc * 16 * 32 + nbase * 32 + lane;
        uint4 bf[8];
#pragma unroll
        for (int nt = 0; nt < 8; nt++) bf[nt] = __ldg(FP + nt * 32);
#pragma unroll
        for (int nt = 0; nt < 8; nt++) MMA_BF16(acc[nt], ah0, ah1, ah2, ah3, bf[nt].x, bf[nt].y);
#pragma unroll
        for (int nt = 0; nt < 8; nt++) MMA_BF16(acc[nt], al0, al1, al2, al3, bf[nt].x, bf[nt].y);
#pragma unroll
        for (int nt = 0; nt < 8; nt++) MMA_BF16(acc[nt], ah0, ah1, ah2, ah3, bf[nt].z, bf[nt].w);
    }

    int grow = rowbase + rloc;
#pragma unroll
    for (int nt = 0; nt < 8; nt++) {
        int col = (nbase + nt) * 8 + kcol;
        if (grow < N_NODES)
            *(__half2*)&dst[grow * 128 + col] = __floats2half2_rn(acc[nt][0], acc[nt][1]);
        if (grow + 8 < N_NODES)
            *(__half2*)&dst[(grow + 8) * 128 + col] = __floats2half2_rn(acc[nt][2], acc[nt][3]);
    }
}

// ---------------- head HMMA GEMM: d_t32 = A @ Wf1, fused apply + fused BN stats ----------------
__global__ void __launch_bounds__(256) k_gemm_head(float* __restrict__ hbuf,
                                                   const float* __restrict__ abuf,
                                                   const uint4* __restrict__ fragP,
                                                   float* __restrict__ dst) {
    extern __shared__ __nv_bfloat16 a_s[];
    const int AS = 128 * 136;
    __shared__ float ssum[8][32], ssq[8][32];
    int tid = threadIdx.x, lane = tid & 31, wid = tid >> 5;
    int rowbase = blockIdx.x * 128;

    fill_A<1, 0, 256>(hbuf, abuf, a_s, AS, rowbase, tid);
    __syncthreads();

    float acc[4][4];
#pragma unroll
    for (int nt = 0; nt < 4; nt++)
#pragma unroll
        for (int j = 0; j < 4; j++) acc[nt][j] = 0.0f;

    int rloc = wid * 16 + (lane >> 2);
    int kcol = (lane & 3) * 2;

#pragma unroll
    for (int kc = 0; kc < 8; kc++) {
        int k0 = kc * 16 + kcol;
        uint32_t ah0 = *(const uint32_t*)&a_s[rloc * 136 + k0];
        uint32_t ah1 = *(const uint32_t*)&a_s[(rloc + 8) * 136 + k0];
        uint32_t ah2 = *(const uint32_t*)&a_s[rloc * 136 + k0 + 8];
        uint32_t ah3 = *(const uint32_t*)&a_s[(rloc + 8) * 136 + k0 + 8];
        uint32_t al0 = *(const uint32_t*)&a_s[AS + rloc * 136 + k0];
        uint32_t al1 = *(const uint32_t*)&a_s[AS + (rloc + 8) * 136 + k0];
        uint32_t al2 = *(const uint32_t*)&a_s[AS + rloc * 136 + k0 + 8];
        uint32_t al3 = *(const uint32_t*)&a_s[AS + (rloc + 8) * 136 + k0 + 8];
        const uint4* FP = fragP + kc * 4 * 32 + lane;
        uint4 bf[4];
#pragma unroll
        for (int nt = 0; nt < 4; nt++) bf[nt] = __ldg(FP + nt * 32);
#pragma unroll
        for (int nt = 0; nt < 4; nt++) MMA_BF16(acc[nt], ah0, ah1, ah2, ah3, bf[nt].x, bf[nt].y);
#pragma unroll
        for (int nt = 0; nt < 4; nt++) MMA_BF16(acc[nt], al0, al1, al2, al3, bf[nt].x, bf[nt].y);
#pragma unroll
        for (int nt = 0; nt < 4; nt++) MMA_BF16(acc[nt], ah0, ah1, ah2, ah3, bf[nt].z, bf[nt].w);
    }

    int grow = rowbase + rloc;
#pragma unroll
    for (int nt = 0; nt < 4; nt++) {
        int col = nt * 8 + kcol;
        if (grow < N_NODES)
            *(float2*)&dst[grow * 32 + col] = make_float2(acc[nt][0], acc[nt][1]);
        if (grow + 8 < N_NODES)
            *(float2*)&dst[(grow + 8) * 32 + col] = make_float2(acc[nt][2], acc[nt][3]);
    }

    // fused BN stats (padding rows contribute zeros)
    float cs[4][2], cq[4][2];
#pragma unroll
    for (int nt = 0; nt < 4; nt++) {
        cs[nt][0] = acc[nt][0] + acc[nt][2];
        cs[nt][1] = acc[nt][1] + acc[nt][3];
        cq[nt][0] = acc[nt][0] * acc[nt][0] + acc[nt][2] * acc[nt][2];
        cq[nt][1] = acc[nt][1] * acc[nt][1] + acc[nt][3] * acc[nt][3];
    }
#pragma unroll
    for (int nt = 0; nt < 4; nt++)
#pragma unroll
        for (int p = 0; p < 2; p++)
#pragma unroll
            for (int off = 4; off < 32; off <<= 1) {
                cs[nt][p] += __shfl_down_sync(0xFFFFFFFFu, cs[nt][p], off);
                cq[nt][p] += __shfl_down_sync(0xFFFFFFFFu, cq[nt][p], off);
            }
    if (lane < 4) {
#pragma unroll
        for (int nt = 0; nt < 4; nt++) {
            ssum[wid][nt * 8 + lane * 2]     = cs[nt][0];
            ssum[wid][nt * 8 + lane * 2 + 1] = cs[nt][1];
            ssq[wid][nt * 8 + lane * 2]      = cq[nt][0];
            ssq[wid][nt * 8 + lane * 2 + 1]  = cq[nt][1];
        }
    }
    __syncthreads();
    if (tid < 32) {
        float S = 0.f, Q = 0.f;
#pragma unroll
        for (int w = 0; w < 8; w++) { S += ssum[w][tid]; Q += ssq[w][tid]; }
        atomicAdd(&d_sumL[3][tid], S);
        atomicAdd(&d_sqL[3][tid], Q);
    }
}

// ---------------- fused aggregation + BN stats (fp32 out) ----------------
__global__ void __launch_bounds__(256) k_agg_stats(int layer) {
    __shared__ float ssum[8][128];
    __shared__ float ssq[8][128];
    int tid = threadIdx.x;
    int wid = tid >> 5, lane = tid & 31;
    const uint2* __restrict__ t2 = (const uint2*)d_t;
    float s0 = 0.f, s1 = 0.f, s2 = 0.f, s3 = 0.f;
    float q0 = 0.f, q1 = 0.f, q2 = 0.f, q3 = 0.f;

    int nwarps = gridDim.x * 8;
    for (int node = blockIdx.x * 8 + wid; node < N_NODES; node += nwarps) {
        float di = d_dinv[node];
        float sl = di * di;
        float4 acc;
        {
            uint2 s = t2[node * 32 + lane];
            float2 p0 = __half22float2(*(__half2*)&s.x);
            float2 p1 = __half22float2(*(__half2*)&s.y);
            acc.x = sl * p0.x; acc.y = sl * p0.y; acc.z = sl * p1.x; acc.w = sl * p1.y;
        }
        int e0 = d_off[node];
        int e1 = e0 + d_cnt[node];
        int j = e0;
        for (; j + 8 <= e1; j += 8) {
            int2 pp[8];
            uint2 uu[8];
#pragma unroll
            for (int u = 0; u < 8; u++) pp[u] = d_epack[j + u];
#pragma unroll
            for (int u = 0; u < 8; u++) uu[u] = __ldg(&t2[pp[u].x * 32 + lane]);
#pragma unroll
            for (int u = 0; u < 8; u++) {
                float w = __int_as_float(pp[u].y);
                float2 a = __half22float2(*(__half2*)&uu[u].x);
                float2 b = __half22float2(*(__half2*)&uu[u].y);
                acc.x += w * a.x; acc.y += w * a.y; acc.z += w * b.x; acc.w += w * b.y;
            }
        }
        for (; j + 4 <= e1; j += 4) {
            int2 pp[4];
            uint2 uu[4];
#pragma unroll
            for (int u = 0; u < 4; u++) pp[u] = d_epack[j + u];
#pragma unroll
            for (int u = 0; u < 4; u++) uu[u] = __ldg(&t2[pp[u].x * 32 + lane]);
#pragma unroll
            for (int u = 0; u < 4; u++) {
                float w = __int_as_float(pp[u].y);
                float2 a = __half22float2(*(__half2*)&uu[u].x);
                float2 b = __half22float2(*(__half2*)&uu[u].y);
                acc.x += w * a.x; acc.y += w * a.y; acc.z += w * b.x; acc.w += w * b.y;
            }
        }
        for (; j < e1; j++) {
            int2 p = d_epack[j];
            float w = __int_as_float(p.y);
            uint2 u = __ldg(&t2[p.x * 32 + lane]);
            float2 a = __half22float2(*(__half2*)&u.x), b = __half22float2(*(__half2*)&u.y);
            acc.x += w * a.x; acc.y += w * a.y; acc.z += w * b.x; acc.w += w * b.y;
        }
        ((float4*)d_a)[node * 32 + lane] = acc;
        s0 += acc.x; q0 += acc.x * acc.x;
        s1 += acc.y; q1 += acc.y * acc.y;
        s2 += acc.z; q2 += acc.z * acc.z;
        s3 += acc.w; q3 += acc.w * acc.w;
    }

    int c0 = lane * 4;
    ssum[wid][c0] = s0; ssum[wid][c0 + 1] = s1; ssum[wid][c0 + 2] = s2; ssum[wid][c0 + 3] = s3;
    ssq[wid][c0]  = q0; ssq[wid][c0 + 1]  = q1; ssq[wid][c0 + 2]  = q2; ssq[wid][c0 + 3]  = q3;
    __syncthreads();
    if (tid < 128) {
        float S = 0.f, Q = 0.f;
#pragma unroll
        for (int w = 0; w < 8; w++) { S += ssum[w][tid]; Q += ssq[w][tid]; }
        atomicAdd(&d_sumL[layer][tid], S);
        atomicAdd(&d_sqL[layer][tid], Q);
    }
}

// ---------------- BN finalize ----------------
__global__ void k_fin128(int layer, const float* __restrict__ g, const float* __restrict__ bt) {
    int c = threadIdx.x;
    float mu  = d_sumL[layer][c] * (1.0f / N_NODES);
    float var = d_sqL[layer][c] * (1.0f / N_NODES) - mu * mu;
    float sc  = g[c] * rsqrtf(var + EPS);
    d_scale[c] = sc;
    d_shift[c] = bt[c] - mu * sc;
}

__global__ void k_fin32(const float* __restrict__ gf, const float* __restrict__ btf) {
    int c = threadIdx.x;
    float mu  = d_sumL[3][c] * (1.0f / N_NODES);
    float var = d_sqL[3][c] * (1.0f / N_NODES) - mu * mu;
    float sc  = gf[c] * rsqrtf(var + EPS);
    d_scale32[c] = sc;
    d_shift32[c] = btf[c] - mu * sc;
}

// ---------------- head: out = tanh(relu(bn(t32)) @ Wf2 + bf2) ----------------
__global__ void k_head(const float* __restrict__ Wf2, const float* __restrict__ bf2,
                       float* __restrict__ out) {
    int n = blockIdx.x * blockDim.x + threadIdx.x;
    if (n >= N_NODES) return;
    float a0 = bf2[0], a1 = bf2[1];
#pragma unroll
    for (int k = 0; k < 32; k++) {
        float f = fmaxf(d_t32[n * 32 + k] * d_scale32[k] + d_shift32[k], 0.0f);
        a0 += f * Wf2[k * 2];
        a1 += f * Wf2[k * 2 + 1];
    }
    out[n * 2]     = tanhf(a0);
    out[n * 2 + 1] = tanhf(a1);
}

// ---------------- launch ----------------
extern "C" void kernel_launch(void* const* d_in, const int* in_sizes, int n_in,
                              void* d_out, int out_size) {
    const float* x   = (const float*)d_in[0];
    const int*   ei  = (const int*)d_in[1];
    const float* We  = (const float*)d_in[2];
    const float* be  = (const float*)d_in[3];
    const float* W1  = (const float*)d_in[4];
    const float* g1  = (const float*)d_in[6];
    const float* bt1 = (const float*)d_in[7];
    const float* W2  = (const float*)d_in[8];
    const float* g2  = (const float*)d_in[10];
    const float* bt2 = (const float*)d_in[11];
    const float* W3  = (const float*)d_in[12];
    const float* g3  = (const float*)d_in[14];
    const float* bt3 = (const float*)d_in[15];
    const float* Wf1 = (const float*)d_in[16];
    const float* gf  = (const float*)d_in[18];
    const float* btf = (const float*)d_in[19];
    const float* Wf2 = (const float*)d_in[20];
    const float* bf2 = (const float*)d_in[21];
    const int* src = ei;
    const int* dst = ei + N_EDGES;
    float* out = (float*)d_out;

    const int DSM = 2 * 128 * 136 * 2;  // 69632 bytes
    cudaFuncSetAttribute(k_gemm_split<0>, cudaFuncAttributeMaxDynamicSharedMemorySize, DSM);
    cudaFuncSetAttribute(k_gemm_split<1>, cudaFuncAttributeMaxDynamicSharedMemorySize, DSM);
    cudaFuncSetAttribute(k_gemm_head,     cudaFuncAttributeMaxDynamicSharedMemorySize, DSM);

    uint4 *fp, *fp32;
    cudaGetSymbolAddress((void**)&fp, d_fragP);
    cudaGetSymbolAddress((void**)&fp32, d_fragP32);
    float *hp, *ap, *t32p;
    __half* tp;
    cudaGetSymbolAddress((void**)&hp, d_h);
    cudaGetSymbolAddress((void**)&ap, d_a);
    cudaGetSymbolAddress((void**)&tp, d_t);
    cudaGetSymbolAddress((void**)&t32p, d_t32);
    const int FSZ = 8 * 16 * 32;
    const int GBLK = (N_NODES + 127) / 128;  // 782
    const int AGGB = 1184;

    // launches 1-3: prerequisites for layer-1 GEMM (profiled slot = launch #4)
    k_wfrag<<<16, 256>>>(W1, fp, 16);                          // 1
    k_encoder<<<N_NODES, 128>>>(x, We, be);                    // 2
    k_zero_cnt<<<(N_NODES + 255) / 256, 256>>>();              // 3
    k_gemm_split<0><<<GBLK, 512, DSM>>>(hp, ap, fp, tp);       // 4  <-- PROFILED

    // CSR build
    k_count<<<(N_EDGES + 255) / 256, 256>>>(dst);
    k_alloc<<<(N_NODES + 255) / 256, 256>>>();
    k_scatter<<<(N_EDGES + 255) / 256, 256>>>(src, dst);

    // remaining weight fragments
    k_wfrag<<<16, 256>>>(W2, fp + FSZ, 16);
    k_wfrag<<<16, 256>>>(W3, fp + 2 * FSZ, 16);
    k_wfrag<<<4, 256>>>(Wf1, fp32, 4);

    const float* gs[3]  = {g1, g2, g3};
    const float* bts[3] = {bt1, bt2, bt3};
    for (int l = 0; l < 3; l++) {
        if (l > 0) k_gemm_split<1><<<GBLK, 512, DSM>>>(hp, ap, fp + l * FSZ, tp);
        k_agg_stats<<<AGGB, 256>>>(l);
        k_fin128<<<1, 128>>>(l, gs[l], bts[l]);
    }

    k_gemm_head<<<GBLK, 256, DSM>>>(hp, ap, fp32, t32p);
    k_fin32<<<1, 32>>>(gf, btf);
    k_head<<<(N_NODES + 255) / 256, 256>>>(Wf2, bf2, out);
}

// round 14
// speedup vs baseline: 1.0599x; 1.0599x over previous
#include <cuda_runtime.h>
#include <cuda_bf16.h>
#include <cuda_fp16.h>
#include <stdint.h>
#include <math.h>

#define N_NODES 100000
#define N_EDGES 1600000
#define HID 128
#define EPS 1e-5f

// ---------------- scratch (static device globals; no allocation) ----------------
__device__ float  d_h[N_NODES * HID];     // current activation (fp32)
__device__ __half d_t[N_NODES * HID];     // h @ W (fp16, pre-aggregation)
__device__ float  d_a[N_NODES * HID];     // aggregated (fp32, pre-BN) — fp16 here FAILS accuracy
__device__ float  d_t32[N_NODES * 32];    // head linear output
__device__ float  d_dinv[N_NODES];
__device__ int    d_cnt[N_NODES];
__device__ int    d_off[N_NODES];
__device__ int    d_cur[N_NODES];
__device__ int    d_total;
__device__ int2   d_epack[N_EDGES];       // {src, __float_as_int(w)}
__device__ float  d_sumL[4][HID], d_sqL[4][HID];
__device__ float  d_scale[HID], d_shift[HID];
__device__ float  d_scale32[32], d_shift32[32];
// fragment-ordered weights for mma.sync: [kc][nt][lane] -> uint2 (b0,b1)
__device__ uint2 d_fragHi[3][8 * 16 * 32];
__device__ uint2 d_fragLo[3][8 * 16 * 32];
__device__ uint2 d_fragHi32[8 * 4 * 32];
__device__ uint2 d_fragLo32[8 * 4 * 32];

// ---------------- CSR build ----------------
__global__ void k_zero_cnt() {
    int i = blockIdx.x * blockDim.x + threadIdx.x;
    if (i < N_NODES) d_cnt[i] = 0;
    if (i < 512) { ((float*)d_sumL)[i] = 0.f; ((float*)d_sqL)[i] = 0.f; }
    if (i == 0) d_total = 0;
}

__global__ void k_count(const int* __restrict__ dst) {
    int e = blockIdx.x * blockDim.x + threadIdx.x;
    if (e < N_EDGES) atomicAdd(&d_cnt[dst[e]], 1);
}

// fused: segment allocation (block scan + global atomic) + dinv + cursor init
__global__ void k_alloc() {
    int i = blockIdx.x * 256 + threadIdx.x;
    int c = (i < N_NODES) ? d_cnt[i] : 0;
    int lane = threadIdx.x & 31, w = threadIdx.x >> 5;
    int v = c;
#pragma unroll
    for (int d = 1; d < 32; d <<= 1) {
        int t = __shfl_up_sync(0xFFFFFFFFu, v, d);
        if (lane >= d) v += t;
    }
    __shared__ int ws[8];
    __shared__ int base;
    if (lane == 31) ws[w] = v;
    __syncthreads();
    if (threadIdx.x == 0) {
        int s = 0;
#pragma unroll
        for (int k = 0; k < 8; k++) { int t = ws[k]; ws[k] = s; s += t; }
        base = atomicAdd(&d_total, s);
    }
    __syncthreads();
    if (i < N_NODES) {
        int o = base + ws[w] + v - c;
        d_off[i] = o;
        d_cur[i] = o;
        d_dinv[i] = rsqrtf((float)(c + 1));
    }
}

__global__ void k_scatter(const int* __restrict__ src, const int* __restrict__ dst) {
    int e = blockIdx.x * blockDim.x + threadIdx.x;
    if (e >= N_EDGES) return;
    int s = src[e], d = dst[e];
    int p = atomicAdd(&d_cur[d], 1);
    d_epack[p] = make_int2(s, __float_as_int(d_dinv[s] * d_dinv[d]));
}

// ---------------- encoder: h = relu(x @ We + be), x is [N,2] ----------------
__global__ void k_encoder(const float* __restrict__ x, const float* __restrict__ We,
                          const float* __restrict__ be) {
    int n = blockIdx.x;
    int c = threadIdx.x;
    float v = x[n * 2] * We[c] + x[n * 2 + 1] * We[HID + c] + be[c];
    d_h[n * HID + c] = fmaxf(v, 0.0f);
}

// ---------------- weight -> mma B-fragment preconvert ----------------
__global__ void k_wfrag(const float* __restrict__ W, uint2* __restrict__ fragHi,
                        uint2* __restrict__ fragLo, int NT) {
    int idx = blockIdx.x * blockDim.x + threadIdx.x;
    int total = 8 * NT * 32;
    if (idx >= total) return;
    int lane = idx & 31;
    int nt = (idx >> 5) % NT;
    int kc = idx / (32 * NT);
    int N = NT * 8;
    int n = nt * 8 + (lane >> 2);
    int k0 = kc * 16 + (lane & 3) * 2;
    float w00 = W[k0 * N + n],      w01 = W[(k0 + 1) * N + n];
    float w10 = W[(k0 + 8) * N + n], w11 = W[(k0 + 9) * N + n];
    __nv_bfloat16 h00 = __float2bfloat16(w00), h01 = __float2bfloat16(w01);
    __nv_bfloat16 h10 = __float2bfloat16(w10), h11 = __float2bfloat16(w11);
    __nv_bfloat16 l00 = __float2bfloat16(w00 - __bfloat162float(h00));
    __nv_bfloat16 l01 = __float2bfloat16(w01 - __bfloat162float(h01));
    __nv_bfloat16 l10 = __float2bfloat16(w10 - __bfloat162float(h10));
    __nv_bfloat16 l11 = __float2bfloat16(w11 - __bfloat162float(h11));
    uint2 hv, lv;
    hv.x = (uint32_t)__bfloat16_as_ushort(h00) | ((uint32_t)__bfloat16_as_ushort(h01) << 16);
    hv.y = (uint32_t)__bfloat16_as_ushort(h10) | ((uint32_t)__bfloat16_as_ushort(h11) << 16);
    lv.x = (uint32_t)__bfloat16_as_ushort(l00) | ((uint32_t)__bfloat16_as_ushort(l01) << 16);
    lv.y = (uint32_t)__bfloat16_as_ushort(l10) | ((uint32_t)__bfloat16_as_ushort(l11) << 16);
    fragHi[idx] = hv;
    fragLo[idx] = lv;
}

#define MMA_BF16(ACC, A0, A1, A2, A3, BX, BY)                                          \
    asm volatile(                                                                      \
        "mma.sync.aligned.m16n8k16.row.col.f32.bf16.bf16.f32 "                         \
        "{%0,%1,%2,%3}, {%4,%5,%6,%7}, {%8,%9}, {%0,%1,%2,%3};"                        \
        : "+f"((ACC)[0]), "+f"((ACC)[1]), "+f"((ACC)[2]), "+f"((ACC)[3])               \
        : "r"(A0), "r"(A1), "r"(A2), "r"(A3), "r"(BX), "r"(BY))

// ---------------- shared A-tile fill: optional fused BN-apply + relu + residual ----------------
template <int APPLY, int WRITEH, int NTHREADS>
__device__ __forceinline__ void fill_A(float* __restrict__ hbuf,
                                       const float* __restrict__ abuf,
                                       __nv_bfloat16* a_s, int AS, int rowbase, int tid) {
    for (int i = tid; i < 128 * 32; i += NTHREADS) {
        int row = i >> 5, cg = i & 31;
        int gr = rowbase + row;
        float4 v = make_float4(0.f, 0.f, 0.f, 0.f);
        if (gr < N_NODES) {
            if (APPLY) {
                float4 a4 = ((const float4*)abuf)[gr * 32 + cg];
                float4 h4 = ((const float4*)hbuf)[gr * 32 + cg];
                int c0 = cg * 4;
                v.x = fmaxf(a4.x * d_scale[c0]     + d_shift[c0],     0.f) + h4.x;
                v.y = fmaxf(a4.y * d_scale[c0 + 1] + d_shift[c0 + 1], 0.f) + h4.y;
                v.z = fmaxf(a4.z * d_scale[c0 + 2] + d_shift[c0 + 2], 0.f) + h4.z;
                v.w = fmaxf(a4.w * d_scale[c0 + 3] + d_shift[c0 + 3], 0.f) + h4.w;
                if (WRITEH) ((float4*)hbuf)[gr * 32 + cg] = v;
            } else {
                v = ((const float4*)hbuf)[gr * 32 + cg];
            }
        }
        __nv_bfloat16 h0 = __float2bfloat16(v.x), h1 = __float2bfloat16(v.y);
        __nv_bfloat16 h2 = __float2bfloat16(v.z), h3 = __float2bfloat16(v.w);
        __nv_bfloat16 l0 = __float2bfloat16(v.x - __bfloat162float(h0));
        __nv_bfloat16 l1 = __float2bfloat16(v.y - __bfloat162float(h1));
        __nv_bfloat16 l2 = __float2bfloat16(v.z - __bfloat162float(h2));
        __nv_bfloat16 l3 = __float2bfloat16(v.w - __bfloat162float(h3));
        int e = row * 136 + cg * 4;
        uint32_t* ph = (uint32_t*)&a_s[e];
        uint32_t* pl = (uint32_t*)&a_s[AS + e];
        ph[0] = (uint32_t)__bfloat16_as_ushort(h0) | ((uint32_t)__bfloat16_as_ushort(h1) << 16);
        ph[1] = (uint32_t)__bfloat16_as_ushort(h2) | ((uint32_t)__bfloat16_as_ushort(h3) << 16);
        pl[0] = (uint32_t)__bfloat16_as_ushort(l0) | ((uint32_t)__bfloat16_as_ushort(l1) << 16);
        pl[1] = (uint32_t)__bfloat16_as_ushort(l2) | ((uint32_t)__bfloat16_as_ushort(l3) << 16);
    }
}

// ---------------- main HMMA GEMM: d_t[fp16] = A @ W, 512 threads, warp=m16n64 ----------------
template <int APPLY>
__global__ void __launch_bounds__(512, 2) k_gemm_split(float* __restrict__ hbuf,
                                                       const float* __restrict__ abuf,
                                                       const uint2* __restrict__ fragHi,
                                                       const uint2* __restrict__ fragLo,
                                                       __half* __restrict__ dst) {
    extern __shared__ __nv_bfloat16 a_s[];  // [2][128][136] bf16 (hi then lo)
    const int AS = 128 * 136;
    int tid = threadIdx.x, lane = tid & 31, wid = tid >> 5;
    int rowbase = blockIdx.x * 128;

    fill_A<APPLY, 1, 512>(hbuf, abuf, a_s, AS, rowbase, tid);
    __syncthreads();

    float acc[8][4];
#pragma unroll
    for (int nt = 0; nt < 8; nt++)
#pragma unroll
        for (int j = 0; j < 4; j++) acc[nt][j] = 0.0f;

    int rloc = (wid >> 1) * 16 + (lane >> 2);
    int kcol = (lane & 3) * 2;
    int nbase = (wid & 1) * 8;

#pragma unroll
    for (int kc = 0; kc < 8; kc++) {
        int k0 = kc * 16 + kcol;
        uint32_t ah0 = *(const uint32_t*)&a_s[rloc * 136 + k0];
        uint32_t ah1 = *(const uint32_t*)&a_s[(rloc + 8) * 136 + k0];
        uint32_t ah2 = *(const uint32_t*)&a_s[rloc * 136 + k0 + 8];
        uint32_t ah3 = *(const uint32_t*)&a_s[(rloc + 8) * 136 + k0 + 8];
        uint32_t al0 = *(const uint32_t*)&a_s[AS + rloc * 136 + k0];
        uint32_t al1 = *(const uint32_t*)&a_s[AS + (rloc + 8) * 136 + k0];
        uint32_t al2 = *(const uint32_t*)&a_s[AS + rloc * 136 + k0 + 8];
        uint32_t al3 = *(const uint32_t*)&a_s[AS + (rloc + 8) * 136 + k0 + 8];
        const uint2* FH = fragHi + kc * 16 * 32 + nbase * 32 + lane;
        const uint2* FL = fragLo + kc * 16 * 32 + nbase * 32 + lane;
        uint2 bh[8];
#pragma unroll
        for (int nt = 0; nt < 8; nt++) bh[nt] = __ldg(FH + nt * 32);
#pragma unroll
        for (int nt = 0; nt < 8; nt++) MMA_BF16(acc[nt], ah0, ah1, ah2, ah3, bh[nt].x, bh[nt].y);
#pragma unroll
        for (int nt = 0; nt < 8; nt++) MMA_BF16(acc[nt], al0, al1, al2, al3, bh[nt].x, bh[nt].y);
        uint2 bl[8];
#pragma unroll
        for (int nt = 0; nt < 8; nt++) bl[nt] = __ldg(FL + nt * 32);
#pragma unroll
        for (int nt = 0; nt < 8; nt++) MMA_BF16(acc[nt], ah0, ah1, ah2, ah3, bl[nt].x, bl[nt].y);
    }

    int grow = rowbase + rloc;
#pragma unroll
    for (int nt = 0; nt < 8; nt++) {
        int col = (nbase + nt) * 8 + kcol;
        if (grow < N_NODES)
            *(__half2*)&dst[grow * 128 + col] = __floats2half2_rn(acc[nt][0], acc[nt][1]);
        if (grow + 8 < N_NODES)
            *(__half2*)&dst[(grow + 8) * 128 + col] = __floats2half2_rn(acc[nt][2], acc[nt][3]);
    }
}

// ---------------- head HMMA GEMM: d_t32 = A @ Wf1, fused apply + fused BN stats ----------------
__global__ void __launch_bounds__(256) k_gemm_head(float* __restrict__ hbuf,
                                                   const float* __restrict__ abuf,
                                                   const uint2* __restrict__ fragHi,
                                                   const uint2* __restrict__ fragLo,
                                                   float* __restrict__ dst) {
    extern __shared__ __nv_bfloat16 a_s[];
    const int AS = 128 * 136;
    __shared__ float ssum[8][32], ssq[8][32];
    int tid = threadIdx.x, lane = tid & 31, wid = tid >> 5;
    int rowbase = blockIdx.x * 128;

    fill_A<1, 0, 256>(hbuf, abuf, a_s, AS, rowbase, tid);
    __syncthreads();

    float acc[4][4];
#pragma unroll
    for (int nt = 0; nt < 4; nt++)
#pragma unroll
        for (int j = 0; j < 4; j++) acc[nt][j] = 0.0f;

    int rloc = wid * 16 + (lane >> 2);
    int kcol = (lane & 3) * 2;

#pragma unroll
    for (int kc = 0; kc < 8; kc++) {
        int k0 = kc * 16 + kcol;
        uint32_t ah0 = *(const uint32_t*)&a_s[rloc * 136 + k0];
        uint32_t ah1 = *(const uint32_t*)&a_s[(rloc + 8) * 136 + k0];
        uint32_t ah2 = *(const uint32_t*)&a_s[rloc * 136 + k0 + 8];
        uint32_t ah3 = *(const uint32_t*)&a_s[(rloc + 8) * 136 + k0 + 8];
        uint32_t al0 = *(const uint32_t*)&a_s[AS + rloc * 136 + k0];
        uint32_t al1 = *(const uint32_t*)&a_s[AS + (rloc + 8) * 136 + k0];
        uint32_t al2 = *(const uint32_t*)&a_s[AS + rloc * 136 + k0 + 8];
        uint32_t al3 = *(const uint32_t*)&a_s[AS + (rloc + 8) * 136 + k0 + 8];
        const uint2* FH = fragHi + kc * 4 * 32 + lane;
        const uint2* FL = fragLo + kc * 4 * 32 + lane;
        uint2 bh[4];
#pragma unroll
        for (int nt = 0; nt < 4; nt++) bh[nt] = __ldg(FH + nt * 32);
#pragma unroll
        for (int nt = 0; nt < 4; nt++) MMA_BF16(acc[nt], ah0, ah1, ah2, ah3, bh[nt].x, bh[nt].y);
#pragma unroll
        for (int nt = 0; nt < 4; nt++) MMA_BF16(acc[nt], al0, al1, al2, al3, bh[nt].x, bh[nt].y);
        uint2 bl[4];
#pragma unroll
        for (int nt = 0; nt < 4; nt++) bl[nt] = __ldg(FL + nt * 32);
#pragma unroll
        for (int nt = 0; nt < 4; nt++) MMA_BF16(acc[nt], ah0, ah1, ah2, ah3, bl[nt].x, bl[nt].y);
    }

    int grow = rowbase + rloc;
#pragma unroll
    for (int nt = 0; nt < 4; nt++) {
        int col = nt * 8 + kcol;
        if (grow < N_NODES)
            *(float2*)&dst[grow * 32 + col] = make_float2(acc[nt][0], acc[nt][1]);
        if (grow + 8 < N_NODES)
            *(float2*)&dst[(grow + 8) * 32 + col] = make_float2(acc[nt][2], acc[nt][3]);
    }

    // fused BN stats (padding rows contribute zeros)
    float cs[4][2], cq[4][2];
#pragma unroll
    for (int nt = 0; nt < 4; nt++) {
        cs[nt][0] = acc[nt][0] + acc[nt][2];
        cs[nt][1] = acc[nt][1] + acc[nt][3];
        cq[nt][0] = acc[nt][0] * acc[nt][0] + acc[nt][2] * acc[nt][2];
        cq[nt][1] = acc[nt][1] * acc[nt][1] + acc[nt][3] * acc[nt][3];
    }
#pragma unroll
    for (int nt = 0; nt < 4; nt++)
#pragma unroll
        for (int p = 0; p < 2; p++)
#pragma unroll
            for (int off = 4; off < 32; off <<= 1) {
                cs[nt][p] += __shfl_down_sync(0xFFFFFFFFu, cs[nt][p], off);
                cq[nt][p] += __shfl_down_sync(0xFFFFFFFFu, cq[nt][p], off);
            }
    if (lane < 4) {
#pragma unroll
        for (int nt = 0; nt < 4; nt++) {
            ssum[wid][nt * 8 + lane * 2]     = cs[nt][0];
            ssum[wid][nt * 8 + lane * 2 + 1] = cs[nt][1];
            ssq[wid][nt * 8 + lane * 2]      = cq[nt][0];
            ssq[wid][nt * 8 + lane * 2 + 1]  = cq[nt][1];
        }
    }
    __syncthreads();
    if (tid < 32) {
        float S = 0.f, Q = 0.f;
#pragma unroll
        for (int w = 0; w < 8; w++) { S += ssum[w][tid]; Q += ssq[w][tid]; }
        atomicAdd(&d_sumL[3][tid], S);
        atomicAdd(&d_sqL[3][tid], Q);
    }
}

// ---------------- fused aggregation + BN stats (fp32 out, pipelined epack prefetch) ----------------
__global__ void __launch_bounds__(256) k_agg_stats(int layer) {
    __shared__ float ssum[8][128];
    __shared__ float ssq[8][128];
    int tid = threadIdx.x;
    int wid = tid >> 5, lane = tid & 31;
    const uint2* __restrict__ t2 = (const uint2*)d_t;
    float s0 = 0.f, s1 = 0.f, s2 = 0.f, s3 = 0.f;
    float q0 = 0.f, q1 = 0.f, q2 = 0.f, q3 = 0.f;

    int nwarps = gridDim.x * 8;
    for (int node = blockIdx.x * 8 + wid; node < N_NODES; node += nwarps) {
        float di = d_dinv[node];
        float sl = di * di;
        float4 acc;
        {
            uint2 s = t2[node * 32 + lane];
            float2 p0 = __half22float2(*(__half2*)&s.x);
            float2 p1 = __half22float2(*(__half2*)&s.y);
            acc.x = sl * p0.x; acc.y = sl * p0.y; acc.z = sl * p1.x; acc.w = sl * p1.y;
        }
        int e0 = d_off[node];
        int e1 = e0 + d_cnt[node];
        int j = e0;

        if (j + 8 <= e1) {
            // software pipeline: epack batch i+1 loads overlap batch i gathers/FMAs
            int2 pc[8];
#pragma unroll
            for (int u = 0; u < 8; u++) pc[u] = d_epack[j + u];
            for (; j + 16 <= e1; j += 8) {
                int2 pn[8];
#pragma unroll
                for (int u = 0; u < 8; u++) pn[u] = d_epack[j + 8 + u];
                uint2 uu[8];
#pragma unroll
                for (int u = 0; u < 8; u++) uu[u] = __ldg(&t2[pc[u].x * 32 + lane]);
#pragma unroll
                for (int u = 0; u < 8; u++) {
                    float w = __int_as_float(pc[u].y);
                    float2 a = __half22float2(*(__half2*)&uu[u].x);
                    float2 b = __half22float2(*(__half2*)&uu[u].y);
                    acc.x += w * a.x; acc.y += w * a.y; acc.z += w * b.x; acc.w += w * b.y;
                }
#pragma unroll
                for (int u = 0; u < 8; u++) pc[u] = pn[u];
            }
            {
                uint2 uu[8];
#pragma unroll
                for (int u = 0; u < 8; u++) uu[u] = __ldg(&t2[pc[u].x * 32 + lane]);
#pragma unroll
                for (int u = 0; u < 8; u++) {
                    float w = __int_as_float(pc[u].y);
                    float2 a = __half22float2(*(__half2*)&uu[u].x);
                    float2 b = __half22float2(*(__half2*)&uu[u].y);
                    acc.x += w * a.x; acc.y += w * a.y; acc.z += w * b.x; acc.w += w * b.y;
                }
                j += 8;
            }
        }
        for (; j + 4 <= e1; j += 4) {
            int2 pp[4];
            uint2 uu[4];
#pragma unroll
            for (int u = 0; u < 4; u++) pp[u] = d_epack[j + u];
#pragma unroll
            for (int u = 0; u < 4; u++) uu[u] = __ldg(&t2[pp[u].x * 32 + lane]);
#pragma unroll
            for (int u = 0; u < 4; u++) {
                float w = __int_as_float(pp[u].y);
                float2 a = __half22float2(*(__half2*)&uu[u].x);
                float2 b = __half22float2(*(__half2*)&uu[u].y);
                acc.x += w * a.x; acc.y += w * a.y; acc.z += w * b.x; acc.w += w * b.y;
            }
        }
        for (; j < e1; j++) {
            int2 p = d_epack[j];
            float w = __int_as_float(p.y);
            uint2 u = __ldg(&t2[p.x * 32 + lane]);
            float2 a = __half22float2(*(__half2*)&u.x), b = __half22float2(*(__half2*)&u.y);
            acc.x += w * a.x; acc.y += w * a.y; acc.z += w * b.x; acc.w += w * b.y;
        }
        ((float4*)d_a)[node * 32 + lane] = acc;
        s0 += acc.x; q0 += acc.x * acc.x;
        s1 += acc.y; q1 += acc.y * acc.y;
        s2 += acc.z; q2 += acc.z * acc.z;
        s3 += acc.w; q3 += acc.w * acc.w;
    }

    int c0 = lane * 4;
    ssum[wid][c0] = s0; ssum[wid][c0 + 1] = s1; ssum[wid][c0 + 2] = s2; ssum[wid][c0 + 3] = s3;
    ssq[wid][c0]  = q0; ssq[wid][c0 + 1]  = q1; ssq[wid][c0 + 2]  = q2; ssq[wid][c0 + 3]  = q3;
    __syncthreads();
    if (tid < 128) {
        float S = 0.f, Q = 0.f;
#pragma unroll
        for (int w = 0; w < 8; w++) { S += ssum[w][tid]; Q += ssq[w][tid]; }
        atomicAdd(&d_sumL[layer][tid], S);
        atomicAdd(&d_sqL[layer][tid], Q);
    }
}

// ---------------- BN finalize ----------------
__global__ void k_fin128(int layer, const float* __restrict__ g, const float* __restrict__ bt) {
    int c = threadIdx.x;
    float mu  = d_sumL[layer][c] * (1.0f / N_NODES);
    float var = d_sqL[layer][c] * (1.0f / N_NODES) - mu * mu;
    float sc  = g[c] * rsqrtf(var + EPS);
    d_scale[c] = sc;
    d_shift[c] = bt[c] - mu * sc;
}

__global__ void k_fin32(const float* __restrict__ gf, const float* __restrict__ btf) {
    int c = threadIdx.x;
    float mu  = d_sumL[3][c] * (1.0f / N_NODES);
    float var = d_sqL[3][c] * (1.0f / N_NODES) - mu * mu;
    float sc  = gf[c] * rsqrtf(var + EPS);
    d_scale32[c] = sc;
    d_shift32[c] = btf[c] - mu * sc;
}

// ---------------- head: out = tanh(relu(bn(t32)) @ Wf2 + bf2) ----------------
__global__ void k_head(const float* __restrict__ Wf2, const float* __restrict__ bf2,
                       float* __restrict__ out) {
    int n = blockIdx.x * blockDim.x + threadIdx.x;
    if (n >= N_NODES) return;
    float a0 = bf2[0], a1 = bf2[1];
#pragma unroll
    for (int k = 0; k < 32; k++) {
        float f = fmaxf(d_t32[n * 32 + k] * d_scale32[k] + d_shift32[k], 0.0f);
        a0 += f * Wf2[k * 2];
        a1 += f * Wf2[k * 2 + 1];
    }
    out[n * 2]     = tanhf(a0);
    out[n * 2 + 1] = tanhf(a1);
}

// ---------------- launch ----------------
extern "C" void kernel_launch(void* const* d_in, const int* in_sizes, int n_in,
                              void* d_out, int out_size) {
    const float* x   = (const float*)d_in[0];
    const int*   ei  = (const int*)d_in[1];
    const float* We  = (const float*)d_in[2];
    const float* be  = (const float*)d_in[3];
    const float* W1  = (const float*)d_in[4];
    const float* g1  = (const float*)d_in[6];
    const float* bt1 = (const float*)d_in[7];
    const float* W2  = (const float*)d_in[8];
    const float* g2  = (const float*)d_in[10];
    const float* bt2 = (const float*)d_in[11];
    const float* W3  = (const float*)d_in[12];
    const float* g3  = (const float*)d_in[14];
    const float* bt3 = (const float*)d_in[15];
    const float* Wf1 = (const float*)d_in[16];
    const float* gf  = (const float*)d_in[18];
    const float* btf = (const float*)d_in[19];
    const float* Wf2 = (const float*)d_in[20];
    const float* bf2 = (const float*)d_in[21];
    const int* src = ei;
    const int* dst = ei + N_EDGES;
    float* out = (float*)d_out;

    const int DSM = 2 * 128 * 136 * 2;  // 69632 bytes
    cudaFuncSetAttribute(k_gemm_split<0>, cudaFuncAttributeMaxDynamicSharedMemorySize, DSM);
    cudaFuncSetAttribute(k_gemm_split<1>, cudaFuncAttributeMaxDynamicSharedMemorySize, DSM);
    cudaFuncSetAttribute(k_gemm_head,     cudaFuncAttributeMaxDynamicSharedMemorySize, DSM);

    uint2 *fh, *fl, *fh32, *fl32;
    cudaGetSymbolAddress((void**)&fh, d_fragHi);
    cudaGetSymbolAddress((void**)&fl, d_fragLo);
    cudaGetSymbolAddress((void**)&fh32, d_fragHi32);
    cudaGetSymbolAddress((void**)&fl32, d_fragLo32);
    float *hp, *ap, *t32p;
    __half* tp;
    cudaGetSymbolAddress((void**)&hp, d_h);
    cudaGetSymbolAddress((void**)&ap, d_a);
    cudaGetSymbolAddress((void**)&tp, d_t);
    cudaGetSymbolAddress((void**)&t32p, d_t32);
    const int FSZ = 8 * 16 * 32;
    const int GBLK = (N_NODES + 127) / 128;  // 782
    const int AGGB = 1184;

    // launches 1-3: prerequisites for layer-1 GEMM (profiled slot = launch #4)
    k_wfrag<<<16, 256>>>(W1, fh, fl, 16);                      // 1
    k_encoder<<<N_NODES, 128>>>(x, We, be);                    // 2
    k_zero_cnt<<<(N_NODES + 255) / 256, 256>>>();              // 3
    k_gemm_split<0><<<GBLK, 512, DSM>>>(hp, ap, fh, fl, tp);   // 4  <-- PROFILED

    // CSR build
    k_count<<<(N_EDGES + 255) / 256, 256>>>(dst);
    k_alloc<<<(N_NODES + 255) / 256, 256>>>();
    k_scatter<<<(N_EDGES + 255) / 256, 256>>>(src, dst);

    // remaining weight fragments
    k_wfrag<<<16, 256>>>(W2, fh + FSZ, fl + FSZ, 16);
    k_wfrag<<<16, 256>>>(W3, fh + 2 * FSZ, fl + 2 * FSZ, 16);
    k_wfrag<<<4, 256>>>(Wf1, fh32, fl32, 4);

    const float* gs[3]  = {g1, g2, g3};
    const float* bts[3] = {bt1, bt2, bt3};
    for (int l = 0; l < 3; l++) {
        if (l > 0) k_gemm_split<1><<<GBLK, 512, DSM>>>(hp, ap, fh + l * FSZ, fl + l * FSZ, tp);
        k_agg_stats<<<AGGB, 256>>>(l);
        k_fin128<<<1, 128>>>(l, gs[l], bts[l]);
    }

    k_gemm_head<<<GBLK, 256, DSM>>>(hp, ap, fh32, fl32, t32p);
    k_fin32<<<1, 32>>>(gf, btf);
    k_head<<<(N_NODES + 255) / 256, 256>>>(Wf2, bf2, out);
}